// round 15
// baseline (speedup 1.0000x reference)
#include <cuda_runtime.h>
#include <cuda_pipeline.h>
#include <cstdint>

#define EPS 1e-10f
#define P_NODES (1u << 20)          // nodes per tree (H*W)
#define THREADS 256
#define MAX_TREES 4
#define T0   2048
#define MID  131072
#define TOPB 524288
#define K1A_GRID 592                // 148 SMs x 4: single resident wave

// Per-node record written once by K1 kernels, read-only afterwards:
//   .x = __float_as_uint(contrib), .y = parent index
__device__ uint2    g_rec[(size_t)MAX_TREES * P_NODES];
// cnt[0]=k1_upper blocks, cnt[1]=k1_lower blocks, cnt[2]=k2 blocks,
// cnt[3]=mid1 blocks, cnt[4]=mid2 blocks
__device__ unsigned g_cnt[8];

__global__ void init_flags() { if (threadIdx.x < 8) g_cnt[threadIdx.x] = 0; }

__device__ __forceinline__ unsigned ld_acq(const unsigned* p) {
    unsigned v;
    asm volatile("ld.acquire.gpu.u32 %0, [%1];" : "=r"(v) : "l"(p));
    return v;
}
__device__ __forceinline__ void wait_cnt(int idx, unsigned tgt) {
    if (threadIdx.x == 0) {
        while (ld_acq(&g_cnt[idx]) < tgt) __nanosleep(256);
    }
    __syncthreads();
}
__device__ __forceinline__ void signal_cnt(int idx) {
    __threadfence();                 // release all prior stores to L2
    __syncthreads();                 // whole block's stores done
    if (threadIdx.x == 0) atomicAdd(&g_cnt[idx], 1u);
}

// ---------------------------------------------------------------------------
// K1 chunk body: 512 nodes at cstart (2 cp.async-staged 256-node sub-chunks).
// ---------------------------------------------------------------------------
__device__ __forceinline__ void k1_chunk(
    const float* __restrict__ x, const float* __restrict__ attrs,
    const int* __restrict__ parents,
    const float* wv, float bv, size_t tb, int cstart,
    float (*stage)[THREADS * 15])
{
    const int NF4 = (THREADS * 15) / 4;             // 960 float4 per 256-node chunk
    const float4* abase = (const float4*)(attrs + tb * 15);

    __syncthreads();                                // stage free (persistent reuse)
    #pragma unroll
    for (int j = 0; j < 2; j++) {
        const float4* src = abase + (size_t)(cstart + j * THREADS) * 15 / 4;
        float4* dst = (float4*)stage[j];
        #pragma unroll
        for (int k = 0; k < 4; k++) {
            const int idx = k * THREADS + threadIdx.x;
            if (idx < NF4) __pipeline_memcpy_async(&dst[idx], &src[idx], 16);
        }
        __pipeline_commit();
    }

    int   p0v, p1v;
    float x0v, x1v;
    {
        const int n0 = cstart + threadIdx.x;
        const int n1 = n0 + THREADS;
        p0v = __ldg(&parents[tb + n0]);  x0v = __ldg(&x[tb + n0]);
        p1v = __ldg(&parents[tb + n1]);  x1v = __ldg(&x[tb + n1]);
    }

    #pragma unroll
    for (int j = 0; j < 2; j++) {
        __pipeline_wait_prior(1 - j);
        __syncthreads();

        const float* a = &stage[j][threadIdx.x * 15];
        float lin = bv;
        lin += a[0]*wv[0] + a[1]*wv[1] + a[2]*wv[2] + a[3]*wv[3] + a[4]*wv[4];
        #pragma unroll
        for (int c = 0; c < 9; c++)
            lin += __logf(fabsf(a[6 + c]) + EPS) * wv[5 + c];
        lin += __fdividef(__fsqrt_rn(a[7]), __fsqrt_rn(a[6]) + EPS) * wv[14];
        float sa, ca;
        __sincosf(a[5], &sa, &ca);
        lin += ca * wv[15] + sa * wv[16];
        const float score = __fdividef(1.0f, 1.0f + __expf(-lin));

        const int   node = cstart + j * THREADS + threadIdx.x;
        const int   p    = j ? p1v : p0v;
        const float xv   = j ? x1v : x0v;
        const float diff = (p == node) ? xv : (xv - __ldg(&x[tb + p]));

        const uint2 rec = make_uint2(__float_as_uint(diff * score), (unsigned)p);
        __stcg((uint2*)&g_rec[tb + node], rec);
    }
}

// ---------------------------------------------------------------------------
// K1-lower: rec [0, TOPB). Normal grid; each block signals cnt[1].
// ---------------------------------------------------------------------------
__global__ __launch_bounds__(THREADS)
void k1_lower(const float* __restrict__ x, const float* __restrict__ weight,
              const float* __restrict__ bias, const float* __restrict__ attrs,
              const int* __restrict__ parents, int N)
{
    __shared__ float stage[2][THREADS * 15];
    const int bpt  = TOPB / 512;                    // 1024 blocks per tree
    const int tree = blockIdx.x / bpt;
    const int cstart = (blockIdx.x - tree * bpt) * 512;
    const size_t tb = (size_t)tree * P_NODES;

    const int n = tree % N;
    float wv[17];
    #pragma unroll
    for (int i = 0; i < 17; i++) wv[i] = __ldg(&weight[n * 17 + i]);
    const float bv = __ldg(&bias[n]);

    k1_chunk(x, attrs, parents, wv, bv, tb, cstart, stage);
    signal_cnt(1);
}

// ---------------------------------------------------------------------------
// K1-upper: rec [TOPB, 1M). Persistent single wave; trigger@entry releases
// the downstream dispatch chain. Each block signals cnt[0] at completion.
// ---------------------------------------------------------------------------
__global__ __launch_bounds__(THREADS, 4)
void k1_upper(const float* __restrict__ x, const float* __restrict__ weight,
              const float* __restrict__ bias, const float* __restrict__ attrs,
              const int* __restrict__ parents, int N, int n_trees)
{
    cudaTriggerProgrammaticLaunchCompletion();
    __shared__ float stage[2][THREADS * 15];

    const int total = n_trees * ((P_NODES - TOPB) / 512);
    for (int ci = blockIdx.x; ci < total; ci += K1A_GRID) {
        const int tree   = ci >> 10;                // 1024 chunks per tree
        const int cstart = TOPB + (ci & 1023) * 512;
        const size_t tb  = (size_t)tree * P_NODES;

        const int n = tree % N;
        float wv[17];
        #pragma unroll
        for (int i = 0; i < 17; i++) wv[i] = __ldg(&weight[n * 17 + i]);
        const float bv = __ldg(&bias[n]);

        k1_chunk(x, attrs, parents, wv, bv, tb, cstart, stage);
    }
    signal_cnt(0);
}

// ---------------------------------------------------------------------------
// K2: [0, T0) per tree via pointer doubling. Data-gated on cnt[1] (k1_lower).
// ---------------------------------------------------------------------------
__global__ __launch_bounds__(1024)
void k2_base(float* __restrict__ out, unsigned tgt1)
{
    cudaTriggerProgrammaticLaunchCompletion();
    wait_cnt(1, tgt1);

    __shared__ float v0[T0 + 1], v1[T0 + 1];
    __shared__ int   p0[T0 + 1], p1[T0 + 1];

    const size_t tb = (size_t)blockIdx.x * P_NODES;

    for (int i = threadIdx.x; i <= T0; i += 1024) {
        if (i < T0) {
            const uint2 r = __ldcg((const uint2*)&g_rec[tb + i]);
            v0[i] = __uint_as_float(r.x);
            p0[i] = (i == 0 || (int)r.y == i) ? T0 : (int)r.y;  // root -> sentinel
        } else { v0[i] = 0.0f; p0[i] = T0; }
    }
    __syncthreads();

    float* cv = v0; float* nv = v1;
    int*   cp = p0; int*   np = p1;
    #pragma unroll 1
    for (int it = 0; it < 11; it++) {
        for (int i = threadIdx.x; i <= T0; i += 1024) {
            const int pp = cp[i];
            nv[i] = cv[i] + cv[pp];
            np[i] = cp[pp];
        }
        __syncthreads();
        float* tv = cv; cv = nv; nv = tv;
        int*   tp = cp; cp = np; np = tp;
    }

    for (int i = threadIdx.x; i < T0; i += 1024)
        out[tb + i] = cv[i];

    signal_cnt(2);
}

// ---------------------------------------------------------------------------
// Walker tier [BASE, BASE + bpt*512): walk chains to < LOW.
// Phase 1 gated on counter w1 (rec producer); (sum, q) held in REGISTERS
// across the phase-2 wait (counter w2: out[<LOW] final); then finalize.
// Optionally signals sig at the end. All waits are forward-only in stream.
// ---------------------------------------------------------------------------
template <int LOW, int BASE>
__global__ __launch_bounds__(THREADS)
void walker(float* __restrict__ out, int bpt,
            int w1, unsigned w1_tgt, int w2, unsigned w2_tgt, int sig)
{
    cudaTriggerProgrammaticLaunchCompletion();
    wait_cnt(w1, w1_tgt);

    const int tree = blockIdx.x / bpt;
    const int lb   = blockIdx.x - tree * bpt;
    const size_t tb = (size_t)tree * P_NODES;
    const int na = BASE + lb * (THREADS * 2) + threadIdx.x;
    const int nb = na + THREADS;

    uint2 ra = __ldcg((const uint2*)&g_rec[tb + na]);
    uint2 rb = __ldcg((const uint2*)&g_rec[tb + nb]);
    float sa = __uint_as_float(ra.x);
    float sb = __uint_as_float(rb.x);
    unsigned qa = ra.y, qb = rb.y;

    #pragma unroll 1
    while (qa >= (unsigned)LOW || qb >= (unsigned)LOW) {
        if (qa >= (unsigned)LOW) {
            const uint2 r = __ldcg((const uint2*)&g_rec[tb + qa]);
            sa += __uint_as_float(r.x);  qa = r.y;
        }
        if (qb >= (unsigned)LOW) {
            const uint2 r = __ldcg((const uint2*)&g_rec[tb + qb]);
            sb += __uint_as_float(r.x);  qb = r.y;
        }
    }

    wait_cnt(w2, w2_tgt);                           // out[< LOW] now final
    out[tb + na] = sa + __ldcg(&out[tb + qa]);
    out[tb + nb] = sb + __ldcg(&out[tb + qb]);

    if (sig >= 0) signal_cnt(sig);
}

// ---------------------------------------------------------------------------
template <typename F, typename... Args>
static inline void launch_pdl(F f, int grid, int block, Args... args)
{
    cudaLaunchConfig_t cfg = {};
    cfg.gridDim  = dim3((unsigned)grid, 1, 1);
    cfg.blockDim = dim3((unsigned)block, 1, 1);
    cudaLaunchAttribute attr[1];
    attr[0].id = cudaLaunchAttributeProgrammaticStreamSerialization;
    attr[0].val.programmaticStreamSerializationAllowed = 1;
    cfg.attrs = attr;
    cfg.numAttrs = 1;
    cudaLaunchKernelEx(&cfg, f, args...);
}

extern "C" void kernel_launch(void* const* d_in, const int* in_sizes, int n_in,
                              void* d_out, int out_size)
{
    const float* x       = (const float*)d_in[0];   // (B,N,H,W) f32
    const float* weight  = (const float*)d_in[1];   // (N,17,1)  f32
    const float* bias    = (const float*)d_in[2];   // (N,1)     f32
    const float* attrs   = (const float*)d_in[3];   // (B,N,P,15) f32
    const int*   parents = (const int*)d_in[4];     // (B,N,P)   i32
    float* out = (float*)d_out;

    const int n_trees = in_sizes[0] / (int)P_NODES; // B*N = 4
    const int N       = in_sizes[1] / 17;

    const unsigned T_LOWER = (unsigned)(n_trees * (TOPB / 512));      // 4096
    const unsigned T_UPPER = (unsigned)K1A_GRID;                      // 592
    const unsigned T_K2    = (unsigned)n_trees;                       // 4
    const int bpt_m1  = (MID  - T0 )  / 512;                          // 252
    const int bpt_m2  = (TOPB - MID)  / 512;                          // 768
    const int bpt_top = ((int)P_NODES - TOPB) / 512;                  // 1024
    const unsigned T_M1 = (unsigned)(n_trees * bpt_m1);
    const unsigned T_M2 = (unsigned)(n_trees * bpt_m2);

    // Plain launches: counters must be zeroed strictly before anything signals.
    init_flags<<<1, 32>>>();
    k1_lower<<<(int)T_LOWER, THREADS>>>(x, weight, bias, attrs, parents, N);

    // PDL chain (dispatch pipelining only; ALL data edges are counter-gated).
    launch_pdl(k1_upper, K1A_GRID, THREADS, x, weight, bias, attrs, parents, N, n_trees);
    launch_pdl(k2_base, n_trees, 1024, out, T_LOWER);
    // mid1 [T0, MID): rec gate = k1_lower (cnt1), out gate = k2 (cnt2), signals cnt3
    launch_pdl(walker<T0, T0>, n_trees * bpt_m1, THREADS,
               out, bpt_m1, 1, T_LOWER, 2, T_K2, 3);
    // mid2 [MID, TOPB): rec gate = cnt1, out gate = mid1 (cnt3), signals cnt4
    launch_pdl(walker<MID, MID>, n_trees * bpt_m2, THREADS,
               out, bpt_m2, 1, T_LOWER, 3, T_M1, 4);
    // top [TOPB, 1M): rec gate = k1_upper (cnt0), out gate = mid2 (cnt4)
    launch_pdl(walker<TOPB, TOPB>, n_trees * bpt_top, THREADS,
               out, bpt_top, 0, T_UPPER, 4, T_M2, -1);
}

// round 17
// speedup vs baseline: 1.2417x; 1.2417x over previous
#include <cuda_runtime.h>
#include <cuda_pipeline.h>
#include <cstdint>

#define EPS 1e-10f
#define P_NODES (1u << 20)          // nodes per tree (H*W)
#define THREADS 256
#define MAX_TREES 4
#define T0 2048                     // resolved by K2 (in-block doubling)

// Per-node record written once by K1, read-only afterwards:
//   .x = __float_as_uint(contrib), .y = parent index
__device__ uint2 g_rec[(size_t)MAX_TREES * P_NODES];

// ---------------------------------------------------------------------------
// K1: contrib[i] = (x[i] - x[parent[i]]) * sigmoid(w . feats(attrs[i]) + b)
// cp.async double-buffered staging, 2 chunks of 256 nodes per block.
// ---------------------------------------------------------------------------
__global__ __launch_bounds__(THREADS)
void k1_contrib(const float* __restrict__ x,
                const float* __restrict__ weight,   // (N,17,1)
                const float* __restrict__ bias,     // (N,1)
                const float* __restrict__ attrs,    // (T,P,15)
                const int*   __restrict__ parents,  // (T,P)
                int N)
{
    __shared__ float stage[2][THREADS * 15];        // 2 x 15 KB
    const int bpt   = P_NODES / (THREADS * 2);      // 2048 blocks per tree
    const int tree  = blockIdx.x / bpt;
    const int c0    = (blockIdx.x - tree * bpt) * 2;
    const size_t tb = (size_t)tree * P_NODES;

    const int n = tree % N;
    float wv[17];
    #pragma unroll
    for (int i = 0; i < 17; i++) wv[i] = __ldg(&weight[n * 17 + i]);
    const float bv = __ldg(&bias[n]);

    const int NF4 = (THREADS * 15) / 4;             // 960 float4 per chunk
    const float4* abase = (const float4*)(attrs + tb * 15);

    #pragma unroll
    for (int j = 0; j < 2; j++) {
        const float4* src = abase + (size_t)(c0 + j) * NF4;
        float4* dst = (float4*)stage[j];
        #pragma unroll
        for (int k = 0; k < 4; k++) {
            const int idx = k * THREADS + threadIdx.x;
            if (idx < NF4) __pipeline_memcpy_async(&dst[idx], &src[idx], 16);
        }
        __pipeline_commit();
    }

    int   p0v, p1v;
    float x0v, x1v;
    {
        const int n0 = c0 * THREADS + threadIdx.x;
        const int n1 = n0 + THREADS;
        p0v = __ldg(&parents[tb + n0]);  x0v = __ldg(&x[tb + n0]);
        p1v = __ldg(&parents[tb + n1]);  x1v = __ldg(&x[tb + n1]);
    }

    #pragma unroll
    for (int j = 0; j < 2; j++) {
        __pipeline_wait_prior(1 - j);
        __syncthreads();

        const float* a = &stage[j][threadIdx.x * 15];
        float lin = bv;
        lin += a[0]*wv[0] + a[1]*wv[1] + a[2]*wv[2] + a[3]*wv[3] + a[4]*wv[4];
        #pragma unroll
        for (int c = 0; c < 9; c++)
            lin += __logf(fabsf(a[6 + c]) + EPS) * wv[5 + c];
        lin += __fdividef(__fsqrt_rn(a[7]), __fsqrt_rn(a[6]) + EPS) * wv[14];
        float sa, ca;
        __sincosf(a[5], &sa, &ca);
        lin += ca * wv[15] + sa * wv[16];
        const float score = __fdividef(1.0f, 1.0f + __expf(-lin));

        const int   node = (c0 + j) * THREADS + threadIdx.x;
        const int   p    = j ? p1v : p0v;
        const float xv   = j ? x1v : x0v;
        const float diff = (p == node) ? xv : (xv - __ldg(&x[tb + p]));

        const uint2 rec = make_uint2(__float_as_uint(diff * score), (unsigned)p);
        __stcg((uint2*)&g_rec[tb + node], rec);
    }
}

// ---------------------------------------------------------------------------
// K2: resolve nodes [0, T0) per tree via pointer doubling in shared memory.
// PDL: triggers successor at entry; syncs on K1 before reading rec.
// ---------------------------------------------------------------------------
__global__ __launch_bounds__(1024)
void k2_base(float* __restrict__ out)
{
    cudaTriggerProgrammaticLaunchCompletion();      // let next tier start its walk
    cudaGridDependencySynchronize();                // rec final (K1 done)

    __shared__ float v0[T0 + 1], v1[T0 + 1];
    __shared__ int   p0[T0 + 1], p1[T0 + 1];

    const size_t tb = (size_t)blockIdx.x * P_NODES;

    for (int i = threadIdx.x; i <= T0; i += 1024) {
        if (i < T0) {
            const uint2 r = g_rec[tb + i];
            v0[i] = __uint_as_float(r.x);
            p0[i] = (i == 0 || (int)r.y == i) ? T0 : (int)r.y;  // root -> sentinel
        } else { v0[i] = 0.0f; p0[i] = T0; }
    }
    __syncthreads();

    float* cv = v0; float* nv = v1;
    int*   cp = p0; int*   np = p1;
    #pragma unroll 1
    for (int it = 0; it < 11; it++) {               // 2^11 >= T0
        for (int i = threadIdx.x; i <= T0; i += 1024) {
            const int pp = cp[i];
            nv[i] = cv[i] + cv[pp];
            np[i] = cp[pp];
        }
        __syncthreads();
        float* tv = cv; cv = nv; nv = tv;
        int*   tp = cp; cp = np; np = tp;
    }

    for (int i = threadIdx.x; i < T0; i += 1024)
        out[tb + i] = cv[i];
}

// ---------------------------------------------------------------------------
// Walk tier [BASE, BASE + bpt*CH*256): walk chains to < LOW (CH chains/thread).
// Walk phase reads only rec (final since K1; kernel dispatch chained via PDL
// trigger-at-entry). Epilogue gridDepSyncs on the previous tier before
// touching out[< LOW]. (sum, q) stay in registers across the sync.
// ---------------------------------------------------------------------------
template <int LOW, int BASE, int CH>
__global__ __launch_bounds__(THREADS)
void walker(float* __restrict__ out, int bpt)
{
    cudaTriggerProgrammaticLaunchCompletion();      // release next tier's dispatch

    const int tree = blockIdx.x / bpt;
    const int lb   = blockIdx.x - tree * bpt;
    const size_t tb = (size_t)tree * P_NODES;
    const int n0 = BASE + lb * (THREADS * CH) + threadIdx.x;

    int      node[CH];
    float    sum[CH];
    unsigned q[CH];
    #pragma unroll
    for (int c = 0; c < CH; c++) {
        node[c] = n0 + c * THREADS;
        const uint2 r = __ldg(&g_rec[tb + node[c]]);
        sum[c] = __uint_as_float(r.x);
        q[c]   = r.y;
    }

    #pragma unroll 1
    for (;;) {
        bool any = false;
        #pragma unroll
        for (int c = 0; c < CH; c++) {
            if (q[c] >= (unsigned)LOW) {
                const uint2 r = __ldg(&g_rec[tb + q[c]]);
                sum[c] += __uint_as_float(r.x);
                q[c] = r.y;
                any = true;
            }
        }
        if (!any) break;
    }

    cudaGridDependencySynchronize();                // out[< LOW] final (prev tier)
    #pragma unroll
    for (int c = 0; c < CH; c++)
        out[tb + node[c]] = sum[c] + __ldg(&out[tb + q[c]]);
}

// ---------------------------------------------------------------------------
template <typename F, typename... Args>
static inline void launch_pdl(F f, int grid, int block, Args... args)
{
    cudaLaunchConfig_t cfg = {};
    cfg.gridDim  = dim3((unsigned)grid, 1, 1);
    cfg.blockDim = dim3((unsigned)block, 1, 1);
    cudaLaunchAttribute attr[1];
    attr[0].id = cudaLaunchAttributeProgrammaticStreamSerialization;
    attr[0].val.programmaticStreamSerializationAllowed = 1;
    cfg.attrs = attr;
    cfg.numAttrs = 1;
    cudaLaunchKernelEx(&cfg, f, args...);
}

extern "C" void kernel_launch(void* const* d_in, const int* in_sizes, int n_in,
                              void* d_out, int out_size)
{
    const float* x       = (const float*)d_in[0];   // (B,N,H,W) f32
    const float* weight  = (const float*)d_in[1];   // (N,17,1)  f32
    const float* bias    = (const float*)d_in[2];   // (N,1)     f32
    const float* attrs   = (const float*)d_in[3];   // (B,N,P,15) f32
    const int*   parents = (const int*)d_in[4];     // (B,N,P)   i32
    float* out = (float*)d_out;

    const int n_trees = in_sizes[0] / (int)P_NODES; // B*N = 4
    const int N       = in_sizes[1] / 17;

    // K1: streaming contrib pass (normal launch; fully completes first)
    k1_contrib<<<n_trees * (P_NODES / (THREADS * 2)), THREADS>>>(x, weight, bias, attrs, parents, N);

    // PDL chain: walk phases overlap; epilogues serialize via gridDepSync.
    launch_pdl(k2_base, n_trees, 1024, out);
    {   // WA: [2048, 16384) -> <2048 (r=8, E~1.38), 2 chains/thread
        const int bpt = (16384 - 2048) / (THREADS * 2);              // 28
        launch_pdl(walker<2048, 2048, 2>, n_trees * bpt, THREADS, out, bpt);
    }
    {   // WB: [16384, 131072) -> <16384 (r=8, E~1.38)
        const int bpt = (131072 - 16384) / (THREADS * 2);            // 224
        launch_pdl(walker<16384, 16384, 2>, n_trees * bpt, THREADS, out, bpt);
    }
    {   // WC: [131072, 262144) -> <131072 (r=2, E~0.39)
        const int bpt = (262144 - 131072) / (THREADS * 2);           // 256
        launch_pdl(walker<131072, 131072, 2>, n_trees * bpt, THREADS, out, bpt);
    }
    {   // WD: [262144, 524288) -> <262144 (r=2, E~0.39)
        const int bpt = (524288 - 262144) / (THREADS * 2);           // 512
        launch_pdl(walker<262144, 262144, 2>, n_trees * bpt, THREADS, out, bpt);
    }
    {   // WE: [524288, 1M) -> <524288 (r=2, E~0.39)
        const int bpt = ((int)P_NODES - 524288) / (THREADS * 2);     // 1024
        launch_pdl(walker<524288, 524288, 2>, n_trees * bpt, THREADS, out, bpt);
    }
}